// round 2
// baseline (speedup 1.0000x reference)
#include <cuda_runtime.h>
#include <math.h>

#define B 64
#define T 512
#define F 512
#define H 1024
#define G4 4096   // 4*H
#define NBLK 128  // persistent blocks (must all be co-resident; 128 <= 148 SMs)

// ---------------- scratch (device globals; no allocations) ----------------
// Precomputed layer-0 input gates (+biases): layout [t][b][4H]
__device__ float g_pre[(size_t)T * B * G4];          // 512 MB
// Recurrent state, TRANSPOSED layout [h][b]; ping-pong by t parity.
__device__ float g_h0A[H * B];
__device__ float g_h0B[H * B];
__device__ float g_h1A[H * B];
__device__ float g_h1B[H * B];
__device__ float g_c0[H * B];
__device__ float g_c1[H * B];
// grid barrier state
__device__ unsigned g_barCnt;
__device__ unsigned g_barGen;

// ---------------- init ----------------
__global__ void init_state() {
    int i = blockIdx.x * blockDim.x + threadIdx.x;
    if (i < H * B) {
        g_h0A[i] = 0.f; g_h1A[i] = 0.f;
        g_c0[i]  = 0.f; g_c1[i]  = 0.f;
    }
    if (i == 0) { g_barCnt = 0u; g_barGen = 0u; }
}

// ---------------- precompute: g_pre = x @ Wi0^T + (bi0+bh0) ----------------
// M = B*T = 32768 (row r = b*T+t), N = 4096, K = 512.
// Block tile 128x64, BK=16, 256 threads, thread tile 8x4.
__global__ void precompute_kernel(const float* __restrict__ x,
                                  const float* __restrict__ Wi,
                                  const float* __restrict__ bi,
                                  const float* __restrict__ bh) {
    __shared__ float xs[16][132];   // [k][m], padded
    __shared__ float ws[16][68];    // [k][n], padded

    const int tid = threadIdx.x;
    const int tx  = tid & 15;          // n group
    const int ty  = tid >> 4;          // m group
    const int n0  = tx * 4;
    const int m0  = ty * 8;
    const int rBase = blockIdx.y * 128;
    const int nBase = blockIdx.x * 64;

    float acc[8][4];
#pragma unroll
    for (int i = 0; i < 8; i++)
#pragma unroll
        for (int j = 0; j < 4; j++) acc[i][j] = 0.f;

    for (int kb = 0; kb < F; kb += 16) {
#pragma unroll
        for (int it = 0; it < 2; it++) {
            int i = tid + it * 256;
            int m = i >> 2, kq = i & 3;
            float4 v = *(const float4*)&x[(size_t)(rBase + m) * F + kb + kq * 4];
            xs[kq * 4 + 0][m] = v.x; xs[kq * 4 + 1][m] = v.y;
            xs[kq * 4 + 2][m] = v.z; xs[kq * 4 + 3][m] = v.w;
        }
        {
            int n = tid >> 2, kq = tid & 3;
            float4 v = *(const float4*)&Wi[(size_t)(nBase + n) * F + kb + kq * 4];
            ws[kq * 4 + 0][n] = v.x; ws[kq * 4 + 1][n] = v.y;
            ws[kq * 4 + 2][n] = v.z; ws[kq * 4 + 3][n] = v.w;
        }
        __syncthreads();
#pragma unroll
        for (int k = 0; k < 16; k++) {
            float4 a0 = *(const float4*)&xs[k][m0];
            float4 a1 = *(const float4*)&xs[k][m0 + 4];
            float4 b4 = *(const float4*)&ws[k][n0];
            float am[8] = {a0.x, a0.y, a0.z, a0.w, a1.x, a1.y, a1.z, a1.w};
            float bn[4] = {b4.x, b4.y, b4.z, b4.w};
#pragma unroll
            for (int i = 0; i < 8; i++)
#pragma unroll
                for (int j = 0; j < 4; j++)
                    acc[i][j] = fmaf(am[i], bn[j], acc[i][j]);
        }
        __syncthreads();
    }

    float bias[4];
#pragma unroll
    for (int j = 0; j < 4; j++) bias[j] = bi[nBase + n0 + j] + bh[nBase + n0 + j];

#pragma unroll
    for (int i = 0; i < 8; i++) {
        int r = rBase + m0 + i;
        int b = r / T;
        int t = r - b * T;
        float4 v;
        v.x = acc[i][0] + bias[0];
        v.y = acc[i][1] + bias[1];
        v.z = acc[i][2] + bias[2];
        v.w = acc[i][3] + bias[3];
        *(float4*)&g_pre[((size_t)t * B + b) * G4 + nBase + n0] = v;
    }
}

// ---------------- grid barrier ----------------
__device__ __forceinline__ void grid_sync() {
    __threadfence();            // make this thread's global writes visible chip-wide
    __syncthreads();
    if (threadIdx.x == 0) {
        unsigned gen = *(volatile unsigned*)&g_barGen;
        unsigned a = atomicAdd(&g_barCnt, 1u);
        if (a == NBLK - 1) {
            g_barCnt = 0u;
            __threadfence();
            atomicAdd(&g_barGen, 1u);
        } else {
            while (*(volatile unsigned*)&g_barGen == gen) { }
        }
    }
    __syncthreads();
}

// ---------------- GEMM-accumulate helper ----------------
// acc[m] += sum_k hin[k][m] * W[j][k]. hin is [H][B] transposed state (read
// via __ldcg: written by other blocks, L1 not coherent). W is [4H][H].
// 256 threads; c = tid&31 -> (q = c>>3 gate, n = c&7 col); mg = tid>>5 -> 8 rows.
__device__ __forceinline__ void gemm_accum(const float* __restrict__ hin,
                                           const float* __restrict__ W,
                                           float acc[8],
                                           int nBase, int c, int m0, int tid,
                                           float hs[32][64], float ws[32][33]) {
    for (int kb = 0; kb < H; kb += 32) {
        __syncthreads();
#pragma unroll
        for (int it = 0; it < 8; it++) {
            int i = tid + it * 256;
            ((float*)hs)[i] = __ldcg(&hin[kb * 64 + i]);
        }
#pragma unroll
        for (int it = 0; it < 4; it++) {
            int i = tid + it * 256;
            int row = i >> 5, kk = i & 31;
            int jr = (row >> 3) * H + nBase + (row & 7);
            ws[kk][row] = W[(size_t)jr * H + kb + kk];
        }
        __syncthreads();
#pragma unroll
        for (int kk = 0; kk < 32; kk++) {
            float w = ws[kk][c];
            float4 ha = *(const float4*)&hs[kk][m0];
            float4 hb = *(const float4*)&hs[kk][m0 + 4];
            acc[0] = fmaf(ha.x, w, acc[0]);
            acc[1] = fmaf(ha.y, w, acc[1]);
            acc[2] = fmaf(ha.z, w, acc[2]);
            acc[3] = fmaf(ha.w, w, acc[3]);
            acc[4] = fmaf(hb.x, w, acc[4]);
            acc[5] = fmaf(hb.y, w, acc[5]);
            acc[6] = fmaf(hb.z, w, acc[6]);
            acc[7] = fmaf(hb.w, w, acc[7]);
        }
    }
}

__device__ __forceinline__ float sigmoidf_(float v) {
    return 1.f / (1.f + expf(-v));
}

// ---------------- persistent LSTM kernel ----------------
// Iteration it runs layer0(t=it) and layer1(t=it-1) back-to-back in each block
// (they touch disjoint buffers), then one grid barrier. 513 iterations total.
__global__ void __launch_bounds__(256, 1)
lstm_persistent(const float* __restrict__ Wh0,
                const float* __restrict__ Wi1,
                const float* __restrict__ Wh1,
                const float* __restrict__ bi1,
                const float* __restrict__ bh1,
                float* __restrict__ out) {
    __shared__ float hs[32][64];
    __shared__ float ws[32][33];
    __shared__ float sg[32][65];

    const int tid = threadIdx.x;
    const int c   = tid & 31;
    const int mg  = tid >> 5;
    const int m0  = mg * 8;
    const int nBase = blockIdx.x * 8;
    const int q = c >> 3, n = c & 7;
    const int j = q * H + nBase + n;

    const float bsum1 = bi1[j] + bh1[j];   // layer-1 bias, fixed per thread

    for (int it = 0; it <= T; it++) {
        // ---- layer 0, t = it ----
        if (it < T) {
            const int t = it;
            const float* hin  = (t & 1) ? g_h0B : g_h0A;
            float*       hout = (t & 1) ? g_h0A : g_h0B;
            const float* pre = &g_pre[(size_t)t * B * G4];

            float acc[8];
#pragma unroll
            for (int i = 0; i < 8; i++) acc[i] = pre[(size_t)(m0 + i) * G4 + j];

            gemm_accum(hin, Wh0, acc, nBase, c, m0, tid, hs, ws);

#pragma unroll
            for (int i = 0; i < 8; i++) sg[c][m0 + i] = acc[i];
            __syncthreads();

#pragma unroll
            for (int e = 0; e < 2; e++) {
                int idx = tid + e * 256;
                int nn = idx >> 6, m = idx & 63;
                float iv = sg[0 * 8 + nn][m];
                float fv = sg[1 * 8 + nn][m];
                float gv = sg[2 * 8 + nn][m];
                float ov = sg[3 * 8 + nn][m];
                int gidx = (nBase + nn) * 64 + m;
                float cP = g_c0[gidx];
                float cN = sigmoidf_(fv) * cP + sigmoidf_(iv) * tanhf(gv);
                float hN = sigmoidf_(ov) * tanhf(cN);
                g_c0[gidx] = cN;
                hout[gidx] = hN;
            }
        }

        // ---- layer 1, t = it-1 (reads h0 written last iteration) ----
        if (it > 0) {
            const int t = it - 1;
            const float* h0new = (t & 1) ? g_h0A : g_h0B;
            const float* h1in  = (t & 1) ? g_h1B : g_h1A;
            float*       h1out = (t & 1) ? g_h1A : g_h1B;

            float acc[8];
#pragma unroll
            for (int i = 0; i < 8; i++) acc[i] = bsum1;

            gemm_accum(h0new, Wi1, acc, nBase, c, m0, tid, hs, ws);
            gemm_accum(h1in,  Wh1, acc, nBase, c, m0, tid, hs, ws);

#pragma unroll
            for (int i = 0; i < 8; i++) sg[c][m0 + i] = acc[i];
            __syncthreads();

#pragma unroll
            for (int e = 0; e < 2; e++) {
                int idx = tid + e * 256;
                int nn = idx >> 6, m = idx & 63;
                float iv = sg[0 * 8 + nn][m];
                float fv = sg[1 * 8 + nn][m];
                float gv = sg[2 * 8 + nn][m];
                float ov = sg[3 * 8 + nn][m];
                int nGlob = nBase + nn;
                int gidx = nGlob * 64 + m;
                float cP = g_c1[gidx];
                float cN = sigmoidf_(fv) * cP + sigmoidf_(iv) * tanhf(gv);
                float hN = sigmoidf_(ov) * tanhf(cN);
                g_c1[gidx] = cN;
                h1out[gidx] = hN;
                out[((size_t)m * T + t) * H + nGlob] = hN;   // out[b][t][h]
            }
        }

        if (it < T) grid_sync();   // last iteration's tail only uses own-block data
    }

    // ---- finals: hT [2,B,H] then cT [2,B,H]. T even -> final h buffers are 'A'.
    // This block wrote its own columns' state; no cross-block reads needed.
    {
        size_t off = (size_t)B * T * H;
        size_t BH = (size_t)B * H;
#pragma unroll
        for (int e = 0; e < 2; e++) {
            int idx = tid + e * 256;
            int nn = idx >> 6, m = idx & 63;
            int hIdx = nBase + nn;
            int gidx = hIdx * 64 + m;
            size_t p = (size_t)m * H + hIdx;
            out[off + p]              = g_h0A[gidx];
            out[off + BH + p]         = g_h1A[gidx];
            out[off + 2 * BH + p]     = g_c0[gidx];
            out[off + 3 * BH + p]     = g_c1[gidx];
        }
    }
}

// ---------------- launch ----------------
extern "C" void kernel_launch(void* const* d_in, const int* in_sizes, int n_in,
                              void* d_out, int out_size) {
    const float* x   = (const float*)d_in[0];
    const float* Wi0 = (const float*)d_in[1];
    const float* Wh0 = (const float*)d_in[2];
    const float* bi0 = (const float*)d_in[3];
    const float* bh0 = (const float*)d_in[4];
    const float* Wi1 = (const float*)d_in[5];
    const float* Wh1 = (const float*)d_in[6];
    const float* bi1 = (const float*)d_in[7];
    const float* bh1 = (const float*)d_in[8];
    float* out = (float*)d_out;

    init_state<<<(H * B + 255) / 256, 256>>>();
    precompute_kernel<<<dim3(G4 / 64, (B * T) / 128), 256>>>(x, Wi0, bi0, bh0);
    lstm_persistent<<<NBLK, 256>>>(Wh0, Wi1, Wh1, bi1, bh1, out);
}